// round 11
// baseline (speedup 1.0000x reference)
#include <cuda_runtime.h>
#include <cuda_bf16.h>
#include <cstdint>

// Flatten 2x2 blocks:
//   out[bc, i*1024 + 4j + 2r + s] = x[bc, 2i+r, 2j+s]
// x: (32, 3, 512, 512) fp32. bc in [0,96), i in [0,256), j in [0,256).
//
// R11: block-size axis probe at the geometry optimum. Confirmed data at
// 2 outputs/thread: 12288x256 = 35.30, 3072x1024 = 34.85 / 33.28.
// Midpoint: 6144 CTAs x 512 threads, each CTA a contiguous 16 KB in /
// 16 KB out strip (4 i-values). Same coalescing: 4 front-batched float2
// loads + 2 STG.128 per thread. Discriminates per-CTA-footprint vs
// wave-count as the mechanism behind the 1024-thread win.

__global__ __launch_bounds__(512)
void flatten2x2_kernel(const float2* __restrict__ x2, float4* __restrict__ out4) {
    unsigned tid = threadIdx.x;                 // 0..511
    unsigned j   = tid & 255u;                  // column-pair index
    unsigned di  = tid >> 8;                    // 0..1: i-pair slot within strip
    unsigned blk = blockIdx.x;                  // 0..6143
    unsigned i0  = (blk & 63u) * 4u + 2u * di;  // this thread: i = i0, i0+1
    unsigned bc  = blk >> 6;                    // 0..95

    // input: float2 units, row stride 256, image stride 131072
    const float2* base = x2 + (size_t)bc * 131072u + (size_t)(2u * i0) * 256u + j;
    float2 a0 = __ldg(base);            // row 2*i0
    float2 b0 = __ldg(base + 256u);     // row 2*i0+1
    float2 a1 = __ldg(base + 512u);     // row 2*i0+2
    float2 b1 = __ldg(base + 768u);     // row 2*i0+3

    // output: float4 units, i stride 256, image stride 65536
    float4* obase = out4 + (size_t)bc * 65536u + (size_t)i0 * 256u + j;
    obase[0]    = make_float4(a0.x, a0.y, b0.x, b0.y);   // i = i0
    obase[256u] = make_float4(a1.x, a1.y, b1.x, b1.y);   // i = i0+1
}

extern "C" void kernel_launch(void* const* d_in, const int* in_sizes, int n_in,
                              void* d_out, int out_size) {
    const float2* x2 = (const float2*)d_in[0];
    float4* out4 = (float4*)d_out;

    // 96 images x 64 strips (4 i-values each) = 6144 CTAs, 512 threads
    flatten2x2_kernel<<<6144, 512>>>(x2, out4);
}

// round 12
// speedup vs baseline: 1.0129x; 1.0129x over previous
#include <cuda_runtime.h>
#include <cuda_bf16.h>
#include <cstdint>

// Flatten 2x2 blocks:
//   out[bc, i*1024 + 4j + 2r + s] = x[bc, 2i+r, 2j+s]
// x: (32, 3, 512, 512) fp32. bc in [0,96), i in [0,256), j in [0,256).
//
// FINAL (R7/R10 geometry, confirmed twice at 33.28 / 34.85 us vs a 35.3+
// plateau for every other configuration). The task is pinned at the
// sustained mixed-R/W DRAM floor: 201 MB compulsory traffic per graph
// replay (bijective permutation, working set 201 MB > 126 MB L2; L2
// residency hints inert without the persisting-L2 carveout, which the
// harness forbids). Sweep results:
//   3072x1024 (this)          33.28 / 34.85
//   24576x256, 12288x256,
//   6144x512                  35.30
//   6144x256 (4/thr)          35.55
//   1536x1024 (4/thr)         35.87
//   296x1024 persistent loop  36.99
// Mechanism: 1024-thread CTAs are an indivisible 8-warp/SMSP scheduling
// unit whose front-batched loads cover one contiguous 32 KB strip,
// maximizing same-region DRAM bursts per scheduler quantum.
//
// Per thread: 4 coalesced float2 loads (lane stride 8B), 2 coalesced
// STG.128 (lane stride 16B). 20 regs, occupancy-unconstrained.

__global__ __launch_bounds__(1024)
void flatten2x2_kernel(const float2* __restrict__ x2, float4* __restrict__ out4) {
    unsigned tid = threadIdx.x;                 // 0..1023
    unsigned j   = tid & 255u;                  // column-pair index
    unsigned di  = tid >> 8;                    // 0..3: i-pair slot within strip
    unsigned blk = blockIdx.x;                  // 0..3071
    unsigned i0  = (blk & 31u) * 8u + 2u * di;  // this thread: i = i0, i0+1
    unsigned bc  = blk >> 5;                    // 0..95

    // input: float2 units, row stride 256, image stride 131072
    const float2* base = x2 + (size_t)bc * 131072u + (size_t)(2u * i0) * 256u + j;
    float2 a0 = __ldg(base);            // row 2*i0
    float2 b0 = __ldg(base + 256u);     // row 2*i0+1
    float2 a1 = __ldg(base + 512u);     // row 2*i0+2
    float2 b1 = __ldg(base + 768u);     // row 2*i0+3

    // output: float4 units, i stride 256, image stride 65536
    float4* obase = out4 + (size_t)bc * 65536u + (size_t)i0 * 256u + j;
    obase[0]    = make_float4(a0.x, a0.y, b0.x, b0.y);   // i = i0
    obase[256u] = make_float4(a1.x, a1.y, b1.x, b1.y);   // i = i0+1
}

extern "C" void kernel_launch(void* const* d_in, const int* in_sizes, int n_in,
                              void* d_out, int out_size) {
    const float2* x2 = (const float2*)d_in[0];
    float4* out4 = (float4*)d_out;

    // 96 images x 32 strips (8 i-values each) = 3072 CTAs, 1024 threads
    flatten2x2_kernel<<<3072, 1024>>>(x2, out4);
}

// round 13
// speedup vs baseline: 1.0222x; 1.0093x over previous
#include <cuda_runtime.h>
#include <cuda_bf16.h>
#include <cstdint>

// Flatten 2x2 blocks:
//   out[bc, i*1024 + 4j + 2r + s] = x[bc, 2i+r, 2j+s]
// x: (32, 3, 512, 512) fp32. bc in [0,96), i in [0,256), j in [0,256).
//
// R13: confirmed geometry optimum (3072 CTAs x 1024 threads, contiguous
// 32 KB strips; 34.85/33.28/34.85 vs >=35.3 for all others) + Blackwell
// 256-bit stores. Each thread produces TWO consecutive output float4s
// (j = 2*j0, 2*j0+1) with one st.global.v8.f32 (32 B/lane, warp covers
// 1024 B per store instruction). Loads: one float4 from row 2i and one
// from row 2i+1 (16 B/lane, coalesced). Halves LDG+STG instruction
// counts, doubles per-instruction burst size.
//
// out float4 (i, 2j0)   = {x[2i,4j0],   x[2i,4j0+1],   x[2i+1,4j0],   x[2i+1,4j0+1]}
// out float4 (i, 2j0+1) = {x[2i,4j0+2], x[2i,4j0+3],   x[2i+1,4j0+2], x[2i+1,4j0+3]}

__global__ __launch_bounds__(1024)
void flatten2x2_kernel(const float4* __restrict__ x4, float4* __restrict__ out4) {
    unsigned tid = threadIdx.x;                 // 0..1023
    unsigned j0  = tid & 127u;                  // j-pair index: j = 2*j0, 2*j0+1
    unsigned di  = tid >> 7;                    // 0..7: i slot within strip
    unsigned blk = blockIdx.x;                  // 0..3071
    unsigned i   = (blk & 31u) * 8u + di;       // i in [0,256)
    unsigned bc  = blk >> 5;                    // 0..95

    // input as float4: row stride 128, image stride 512*128 = 65536
    const float4* base = x4 + (size_t)bc * 65536u + (size_t)(2u * i) * 128u + j0;
    float4 a = __ldg(base);          // row 2i,   cols 4j0..4j0+3
    float4 b = __ldg(base + 128u);   // row 2i+1, cols 4j0..4j0+3

    // output: float4 units, i stride 256, image stride 65536
    float4* op = out4 + (size_t)bc * 65536u + (size_t)i * 256u + 2u * j0;
    // one 256-bit store: {a.x,a.y,b.x,b.y, a.z,a.w,b.z,b.w}
    asm volatile(
        "st.global.v8.f32 [%0], {%1,%2,%3,%4,%5,%6,%7,%8};"
        :: "l"(op),
           "f"(a.x), "f"(a.y), "f"(b.x), "f"(b.y),
           "f"(a.z), "f"(a.w), "f"(b.z), "f"(b.w)
        : "memory");
}

extern "C" void kernel_launch(void* const* d_in, const int* in_sizes, int n_in,
                              void* d_out, int out_size) {
    const float4* x4 = (const float4*)d_in[0];
    float4* out4 = (float4*)d_out;

    // 96 images x 32 strips (8 i-values each) = 3072 CTAs, 1024 threads
    flatten2x2_kernel<<<3072, 1024>>>(x4, out4);
}